// round 5
// baseline (speedup 1.0000x reference)
#include <cuda_runtime.h>
#include <cuda_fp16.h>
#include <mma.h>
#include <math.h>

using namespace nvcuda;

#define Nn  20000
#define Ee  80000
#define Hh  64
#define NFf 32
#define Bb  64
#define HID 128

// ---------------- device scratch (no allocations allowed) ----------------
__device__ float  g_X[Nn * Hh];
__device__ float  g_agg[Nn * Hh];              // zeroed at load; k_gru re-zeroes after use
__device__ __half g_hid[Ee * HID];             // edge MLP hidden (fp16)
__device__ __half g_w2h[HID * Hh * Hh];        // W2 in fp16 (1 MB)
__device__ __half g_we[(size_t)Ee * Hh * Hh];  // 655 MB edge weights (fp16)
__device__ float  g_deg[Nn];
__device__ int    g_cnt[Bb];
__device__ int    g_ptr[Bb + 1];
__device__ float  g_en[Nn];
__device__ float  g_hs[Bb * Hh];
__device__ float  g_cs[Bb * Hh];
__device__ float  g_qstar[Bb * 2 * Hh];

__device__ __forceinline__ float sigf(float x) { return 1.0f / (1.0f + expf(-x)); }

// ---------------- prep: W2 -> fp16 ----------------
__global__ void k_prep(const float* __restrict__ w2) {
    int i4 = (blockIdx.x * 256 + threadIdx.x) * 4;
    float4 v = *(const float4*)&w2[i4];
    *(__half2*)&g_w2h[i4]     = __floats2half2_rn(v.x, v.y);
    *(__half2*)&g_w2h[i4 + 2] = __floats2half2_rn(v.z, v.w);
}

// ---------------- lin0: X = relu(x @ W0 + b0) ----------------
__global__ void k_lin0(const float* __restrict__ x, const float* __restrict__ w,
                       const float* __restrict__ b) {
    __shared__ float xs[NFf];
    int n = blockIdx.x, o = threadIdx.x;           // 64 threads
    if (o < NFf) xs[o] = x[n * NFf + o];
    __syncthreads();
    float acc = b[o];
#pragma unroll
    for (int i = 0; i < NFf; i++) acc = fmaf(xs[i], w[i * Hh + o], acc);
    g_X[n * Hh + o] = fmaxf(acc, 0.0f);
}

// ---------------- edge MLP layer 1: hid = fp16(relu(edge_attr @ W1 + b1)) ----------------
__global__ void k_mlp1(const float* __restrict__ ea, const float* __restrict__ w,
                       const float* __restrict__ b) {
    __shared__ float es[Hh];
    int e = blockIdx.x, j = threadIdx.x;           // 128 threads
    if (j < Hh) es[j] = ea[e * Hh + j];
    __syncthreads();
    float acc = b[j];
#pragma unroll
    for (int i = 0; i < Hh; i++) acc = fmaf(es[i], w[i * HID + j], acc);
    g_hid[e * HID + j] = __float2half_rn(fmaxf(acc, 0.0f));
}

// ---------------- big GEMM (fp16 HMMA): we = fp16(hid @ W2 + b2) ----------------
// C [80000 x 4096] = A [80000 x 128](h) * B [128 x 4096](h), fp32 accum
// Block: 128x64 tile, 8 warps each 32x32 (2x2 fragments). Bias pre-loaded into acc.
#define GBM 128
#define GBN 64
#define GBK 64
#define AST 72          // half stride for A/B smem tiles
#define CST 66          // float stride for epilogue staging
#define SMEM_BYTES 34816
__global__ __launch_bounds__(256)
void k_gemm_we(const float* __restrict__ bias) {
    __shared__ __align__(16) char smem[SMEM_BYTES];
    __half* As = (__half*)smem;                         // 128 x 72 half = 18432 B
    __half* Bs = (__half*)(smem + 18432);               // 64 x 72 half  =  9216 B
    float*  bias_s = (float*)(smem + 27648);            // 16 x 68 float =  4352 B
    float*  Cs = (float*)smem;                          // 128 x 66 float (epilogue, aliases all)

    int bn = blockIdx.x;            // 0..63  col tile
    int bm = blockIdx.y;            // 0..624 row tile
    int t  = threadIdx.x;           // 256
    int wid = t >> 5;
    int wr = wid >> 1;              // warp row 0..3 (32 rows each)
    int wc = wid & 1;               // warp col 0..1 (32 cols each)

    // bias tile: 16 identical rows of bias[bn*64 .. +63]
    if (t < Hh) {
        float bv = bias[bn * GBN + t];
#pragma unroll
        for (int r = 0; r < 16; r++) bias_s[r * 68 + t] = bv;
    }
    __syncthreads();

    wmma::fragment<wmma::accumulator, 16, 16, 16, float> c00, c01, c10, c11;
    wmma::load_matrix_sync(c00, &bias_s[wc * 32],      68, wmma::mem_row_major);
    wmma::load_matrix_sync(c01, &bias_s[wc * 32 + 16], 68, wmma::mem_row_major);
    wmma::load_matrix_sync(c10, &bias_s[wc * 32],      68, wmma::mem_row_major);
    wmma::load_matrix_sync(c11, &bias_s[wc * 32 + 16], 68, wmma::mem_row_major);

    const __half* A = g_hid + (size_t)bm * GBM * HID;
    const __half* Bg = g_w2h + bn * GBN;

    for (int kt = 0; kt < HID; kt += GBK) {
        __syncthreads();   // protect bias_s (first iter) / previous-iter tiles
        // A: 128 rows x 64 halves = 1024 float4, 4 per thread
#pragma unroll
        for (int p = 0; p < 4; p++) {
            int idx = p * 256 + t;
            int r = idx >> 3, c8 = (idx & 7) * 8;
            *(float4*)&As[r * AST + c8] = *(const float4*)&A[r * HID + kt + c8];
        }
        // B: 64 rows x 64 halves = 512 float4, 2 per thread
#pragma unroll
        for (int p = 0; p < 2; p++) {
            int idx = p * 256 + t;
            int r = idx >> 3, c8 = (idx & 7) * 8;
            *(float4*)&Bs[r * AST + c8] = *(const float4*)&Bg[(size_t)(kt + r) * (Hh * Hh) + c8];
        }
        __syncthreads();
#pragma unroll
        for (int k16 = 0; k16 < GBK / 16; k16++) {
            wmma::fragment<wmma::matrix_a, 16, 16, 16, __half, wmma::row_major> af0, af1;
            wmma::fragment<wmma::matrix_b, 16, 16, 16, __half, wmma::row_major> bf0, bf1;
            wmma::load_matrix_sync(af0, &As[(wr * 32) * AST + k16 * 16], AST);
            wmma::load_matrix_sync(af1, &As[(wr * 32 + 16) * AST + k16 * 16], AST);
            wmma::load_matrix_sync(bf0, &Bs[(k16 * 16) * AST + wc * 32], AST);
            wmma::load_matrix_sync(bf1, &Bs[(k16 * 16) * AST + wc * 32 + 16], AST);
            wmma::mma_sync(c00, af0, bf0, c00);
            wmma::mma_sync(c01, af0, bf1, c01);
            wmma::mma_sync(c10, af1, bf0, c10);
            wmma::mma_sync(c11, af1, bf1, c11);
        }
    }
    __syncthreads();

    // epilogue: fragments -> Cs (float) -> half global
    wmma::store_matrix_sync(&Cs[(wr * 32) * CST + wc * 32],          c00, CST, wmma::mem_row_major);
    wmma::store_matrix_sync(&Cs[(wr * 32) * CST + wc * 32 + 16],     c01, CST, wmma::mem_row_major);
    wmma::store_matrix_sync(&Cs[(wr * 32 + 16) * CST + wc * 32],     c10, CST, wmma::mem_row_major);
    wmma::store_matrix_sync(&Cs[(wr * 32 + 16) * CST + wc * 32 + 16], c11, CST, wmma::mem_row_major);
    __syncthreads();

    __half* C = g_we + (size_t)bm * GBM * (Hh * Hh) + bn * GBN;
#pragma unroll
    for (int p = 0; p < 8; p++) {
        int idx = p * 256 + t;          // 2048 units of 4 cols
        int r = idx >> 4, c = (idx & 15) * 4;
        float2 v0 = *(float2*)&Cs[r * CST + c];
        float2 v1 = *(float2*)&Cs[r * CST + c + 2];
        __half2 h0 = __floats2half2_rn(v0.x, v0.y);
        __half2 h1 = __floats2half2_rn(v1.x, v1.y);
        uint2 pk = make_uint2(*(unsigned*)&h0, *(unsigned*)&h1);
        *(uint2*)&C[(size_t)r * (Hh * Hh) + c] = pk;
    }
}

// ---------------- degree / batch counts ----------------
__global__ void k_deg(const int* __restrict__ dst) {
    int e = blockIdx.x * blockDim.x + threadIdx.x;
    if (e < Ee) atomicAdd(&g_deg[dst[e]], 1.0f);
}
__global__ void k_cnt(const int* __restrict__ batch) {
    int n = blockIdx.x * blockDim.x + threadIdx.x;
    if (n < Nn) atomicAdd(&g_cnt[batch[n]], 1);
}
__global__ void k_scan() {
    int t = threadIdx.x;           // 256 threads
    if (t == 0) {
        g_ptr[0] = 0;
        for (int b = 0; b < Bb; b++) g_ptr[b + 1] = g_ptr[b] + g_cnt[b];
    }
    for (int i = t; i < Bb * Hh; i += 256) { g_hs[i] = 0.0f; g_cs[i] = 0.0f; }
    for (int i = t; i < Bb * 2 * Hh; i += 256) g_qstar[i] = 0.0f;
}

// ---------------- per-edge matvec + scatter: 4 edges/block, 16B streaming loads ----------------
__global__ __launch_bounds__(256)
void k_msg(const int* __restrict__ src, const int* __restrict__ dst) {
    __shared__ float xs[4][Hh];
    __shared__ float red[4][8][Hh];
    int t = threadIdx.x;                    // 256
    int le = t >> 6;                        // local edge 0..3
    int u  = t & 63;                        // lane within edge
    int e  = blockIdx.x * 4 + le;
    int s = src[e], d = dst[e];
    xs[le][u] = g_X[s * Hh + u];
    __syncthreads();
    const __half* we = g_we + (size_t)e * Hh * Hh;
    int g = u >> 3, c8 = (u & 7) * 8;
    float acc[8] = {};
#pragma unroll
    for (int i = 0; i < 8; i++) {
        int ii = i * 8 + g;
        float xv = xs[le][ii];
        uint4 raw = __ldcs((const uint4*)&we[ii * Hh + c8]);
        const __half2* hp = (const __half2*)&raw;
#pragma unroll
        for (int j = 0; j < 4; j++) {
            float2 f = __half22float2(hp[j]);
            acc[2 * j]     = fmaf(xv, f.x, acc[2 * j]);
            acc[2 * j + 1] = fmaf(xv, f.y, acc[2 * j + 1]);
        }
    }
    *(float4*)&red[le][g][c8]     = make_float4(acc[0], acc[1], acc[2], acc[3]);
    *(float4*)&red[le][g][c8 + 4] = make_float4(acc[4], acc[5], acc[6], acc[7]);
    __syncthreads();
    float v = 0.0f;
#pragma unroll
    for (int g2 = 0; g2 < 8; g2++) v += red[le][g2][u];
    atomicAdd(&g_agg[d * Hh + u], v);
}

// ---------------- fused m = relu(agg/deg + X@root + cb) ; X = GRU(m, X) ----------------
__global__ void k_gru(const float* __restrict__ cr, const float* __restrict__ cb,
                      const float* __restrict__ wih, const float* __restrict__ whh,
                      const float* __restrict__ bih, const float* __restrict__ bhh) {
    __shared__ float xs[Hh], ms[Hh], gi[3 * Hh], gh[3 * Hh];
    int n = blockIdx.x, t = threadIdx.x;           // 192 threads
    if (t < Hh) xs[t] = g_X[n * Hh + t];
    __syncthreads();
    if (t < Hh) {
        float d = fmaxf(g_deg[n], 1.0f);
        float acc = g_agg[n * Hh + t] / d + cb[t];
        g_agg[n * Hh + t] = 0.0f;
#pragma unroll
        for (int i = 0; i < Hh; i++) acc = fmaf(xs[i], cr[i * Hh + t], acc);
        ms[t] = fmaxf(acc, 0.0f);
    }
    __syncthreads();
    {
        float a = bih[t], c = bhh[t];
#pragma unroll
        for (int i = 0; i < Hh; i++) {
            a = fmaf(ms[i], wih[i * 3 * Hh + t], a);
            c = fmaf(xs[i], whh[i * 3 * Hh + t], c);
        }
        gi[t] = a; gh[t] = c;
    }
    __syncthreads();
    if (t < Hh) {
        float r = sigf(gi[t] + gh[t]);
        float z = sigf(gi[Hh + t] + gh[Hh + t]);
        float ng = tanhf(gi[2 * Hh + t] + r * gh[2 * Hh + t]);
        g_X[n * Hh + t] = (1.0f - z) * ng + z * xs[t];
    }
}

// ---------------- Set2Set LSTM step ----------------
__global__ void k_lstm(const float* __restrict__ wih, const float* __restrict__ whh,
                       const float* __restrict__ bih, const float* __restrict__ bhh) {
    __shared__ float qs[2 * Hh], hr[Hh], g[4 * Hh];
    int b = blockIdx.x, t = threadIdx.x;           // 256 threads
    if (t < 2 * Hh) qs[t] = g_qstar[b * 2 * Hh + t];
    if (t < Hh) hr[t] = g_hs[b * Hh + t];
    __syncthreads();
    {
        float a = bih[t] + bhh[t];
#pragma unroll
        for (int i = 0; i < 2 * Hh; i++) a = fmaf(qs[i], wih[i * 4 * Hh + t], a);
#pragma unroll
        for (int i = 0; i < Hh; i++) a = fmaf(hr[i], whh[i * 4 * Hh + t], a);
        g[t] = a;
    }
    __syncthreads();
    if (t < Hh) {
        float ii = sigf(g[t]);
        float ff = sigf(g[Hh + t]);
        float gg = tanhf(g[2 * Hh + t]);
        float oo = sigf(g[3 * Hh + t]);
        float c2 = ff * g_cs[b * Hh + t] + ii * gg;
        float h2 = oo * tanhf(c2);
        g_cs[b * Hh + t] = c2;
        g_hs[b * Hh + t] = h2;
        g_qstar[b * 2 * Hh + t] = h2;
    }
}

// ---------------- en[n] = dot(X[n], hs[batch[n]]) ----------------
__global__ void k_en(const int* __restrict__ batch) {
    __shared__ float red[2];
    int n = blockIdx.x, o = threadIdx.x;           // 64 threads
    int b = batch[n];
    float v = g_X[n * Hh + o] * g_hs[b * Hh + o];
#pragma unroll
    for (int s = 16; s > 0; s >>= 1) v += __shfl_down_sync(0xffffffffu, v, s);
    if ((o & 31) == 0) red[o >> 5] = v;
    __syncthreads();
    if (o == 0) g_en[n] = red[0] + red[1];
}

// ---------------- per-graph softmax + weighted readout ----------------
__global__ void k_pool() {
    __shared__ float sm[Hh];
    int b = blockIdx.x, t = threadIdx.x;           // 64 threads
    int s = g_ptr[b], e = g_ptr[b + 1];
    float m = -1e30f;
    for (int n = s + t; n < e; n += Hh) m = fmaxf(m, g_en[n]);
    sm[t] = m; __syncthreads();
    for (int st = 32; st > 0; st >>= 1) { if (t < st) sm[t] = fmaxf(sm[t], sm[t + st]); __syncthreads(); }
    float mx = sm[0]; __syncthreads();
    float ss = 0.0f;
    for (int n = s + t; n < e; n += Hh) ss += expf(g_en[n] - mx);
    sm[t] = ss; __syncthreads();
    for (int st = 32; st > 0; st >>= 1) { if (t < st) sm[t] += sm[t + st]; __syncthreads(); }
    float inv = 1.0f / (sm[0] + 1e-16f);
    float acc = 0.0f;
    for (int n = s; n < e; n++) {
        float a = expf(g_en[n] - mx) * inv;
        acc = fmaf(a, g_X[n * Hh + t], acc);
    }
    g_qstar[b * 2 * Hh + Hh + t] = acc;
}

// ---------------- head ----------------
__global__ void k_final(const float* __restrict__ w1, const float* __restrict__ b1,
                        const float* __restrict__ w2, const float* __restrict__ b2,
                        float* __restrict__ out) {
    __shared__ float qs[2 * Hh], red[Hh];
    int b = blockIdx.x, t = threadIdx.x;           // 64 threads
    qs[t] = g_qstar[b * 2 * Hh + t];
    qs[Hh + t] = g_qstar[b * 2 * Hh + Hh + t];
    __syncthreads();
    float a = b1[t];
#pragma unroll
    for (int i = 0; i < 2 * Hh; i++) a = fmaf(qs[i], w1[i * Hh + t], a);
    a = fmaxf(a, 0.0f);
    red[t] = a * w2[t];
    __syncthreads();
    for (int st = 32; st > 0; st >>= 1) { if (t < st) red[t] += red[t + st]; __syncthreads(); }
    if (t == 0) out[b] = red[0] + b2[0];
}

// ---------------- launcher ----------------
extern "C" void kernel_launch(void* const* d_in, const int* in_sizes, int n_in,
                              void* d_out, int out_size) {
    const float* x         = (const float*)d_in[0];
    const int*   ei        = (const int*)d_in[1];
    const int*   batch     = (const int*)d_in[2];
    const float* edge_attr = (const float*)d_in[3];
    const float* lin0_w = (const float*)d_in[4];
    const float* lin0_b = (const float*)d_in[5];
    const float* nn_w1  = (const float*)d_in[6];
    const float* nn_b1  = (const float*)d_in[7];
    const float* nn_w2  = (const float*)d_in[8];
    const float* nn_b2  = (const float*)d_in[9];
    const float* conv_root = (const float*)d_in[10];
    const float* conv_bias = (const float*)d_in[11];
    const float* gru_wih = (const float*)d_in[12];
    const float* gru_whh = (const float*)d_in[13];
    const float* gru_bih = (const float*)d_in[14];
    const float* gru_bhh = (const float*)d_in[15];
    const float* lstm_wih = (const float*)d_in[16];
    const float* lstm_whh = (const float*)d_in[17];
    const float* lstm_bih = (const float*)d_in[18];
    const float* lstm_bhh = (const float*)d_in[19];
    const float* lin1_w = (const float*)d_in[20];
    const float* lin1_b = (const float*)d_in[21];
    const float* lin2_w = (const float*)d_in[22];
    const float* lin2_b = (const float*)d_in[23];

    const int* src = ei;
    const int* dst = ei + Ee;

    void *p_deg, *p_cnt;
    cudaGetSymbolAddress(&p_deg, g_deg);
    cudaGetSymbolAddress(&p_cnt, g_cnt);
    cudaMemsetAsync(p_deg, 0, Nn * sizeof(float), 0);
    cudaMemsetAsync(p_cnt, 0, Bb * sizeof(int), 0);

    // launch #4 (k_gemm_we) is the ncu-profiled one
    k_prep<<<512, 256>>>(nn_w2);                                     // 1
    k_lin0<<<Nn, Hh>>>(x, lin0_w, lin0_b);                           // 2
    k_mlp1<<<Ee, HID>>>(edge_attr, nn_w1, nn_b1);                    // 3
    k_gemm_we<<<dim3((Hh * Hh) / GBN, Ee / GBM), 256>>>(nn_b2);      // 4 <- profiled
    k_deg<<<(Ee + 255) / 256, 256>>>(dst);                           // 5
    k_cnt<<<(Nn + 255) / 256, 256>>>(batch);                         // 6
    k_scan<<<1, 256>>>();                                            // 7

    for (int it = 0; it < 3; it++) {
        k_msg<<<Ee / 4, 256>>>(src, dst);
        k_gru<<<Nn, 3 * Hh>>>(conv_root, conv_bias, gru_wih, gru_whh, gru_bih, gru_bhh);
    }

    for (int st = 0; st < 3; st++) {
        k_lstm<<<Bb, 4 * Hh>>>(lstm_wih, lstm_whh, lstm_bih, lstm_bhh);
        k_en<<<Nn, Hh>>>(batch);
        k_pool<<<Bb, Hh>>>();
    }

    k_final<<<Bb, Hh>>>(lin1_w, lin1_b, lin2_w, lin2_b, (float*)d_out);
}